// round 14
// baseline (speedup 1.0000x reference)
#include <cuda_runtime.h>
#include <cuda_fp16.h>
#include <math.h>

// Problem constants
#define BB   2
#define SS   2048
#define DD   1024
#define HH   16
#define DH   64
#define MM   (BB*SS)     // 4096
#define BH   (BB*HH)     // 32

typedef __half h16;
typedef unsigned uns;

// ---------------------------------------------------------------------------
// Scratch arena (device globals: allocation-free)
// ---------------------------------------------------------------------------
#define CHK (1u<<22)
#define WCH (1u<<20)
__device__ h16 g_hf[(size_t)9*CHK + 8*WCH];
__device__ unsigned g_mbits[(size_t)SS*SS/32];

// ---------------------------------------------------------------------------
// helpers
// ---------------------------------------------------------------------------
__device__ __forceinline__ unsigned smem_u32(const void* p){
    unsigned r;
    asm("{ .reg .u64 t; cvta.to.shared.u64 t, %1; cvt.u32.u64 %0, t; }"
        : "=r"(r) : "l"(p));
    return r;
}
#define CP16(dst,src) asm volatile("cp.async.cg.shared.global [%0], [%1], 16;\n" :: "r"(dst), "l"(src))
#define CPCOMMIT()    asm volatile("cp.async.commit_group;\n")
#define CPWAIT(N)     asm volatile("cp.async.wait_group %0;\n" :: "n"(N))

__device__ __forceinline__ uns pkf(float a, float b){
    __half2 t = __floats2half2_rn(a, b);
    return *(uns*)&t;
}
__device__ __forceinline__ uns pkh(h16 a, h16 b){
    return (uns)__half_as_ushort(a) | ((uns)__half_as_ushort(b) << 16);
}
__device__ __forceinline__ void hsplit(float x, h16 &h, h16 &l){
    h = __float2half_rn(x);
    l = __float2half_rn(x - __half2float(h));
}

__device__ __forceinline__ void mma_f16(float c[4], const uns a[4], const uns b0, const uns b1){
    asm volatile("mma.sync.aligned.m16n8k16.row.col.f32.f16.f16.f32 "
        "{%0,%1,%2,%3}, {%4,%5,%6,%7}, {%8,%9}, {%0,%1,%2,%3};"
        : "+f"(c[0]),"+f"(c[1]),"+f"(c[2]),"+f"(c[3])
        : "r"(a[0]),"r"(a[1]),"r"(a[2]),"r"(a[3]),"r"(b0),"r"(b1));
}
__device__ __forceinline__ void ldm4(uns r[4], uns addr){
    asm volatile("ldmatrix.sync.aligned.m8n8.x4.shared.b16 {%0,%1,%2,%3}, [%4];"
        : "=r"(r[0]),"=r"(r[1]),"=r"(r[2]),"=r"(r[3]) : "r"(addr));
}
__device__ __forceinline__ void ldm2(uns r[2], uns addr){
    asm volatile("ldmatrix.sync.aligned.m8n8.x2.shared.b16 {%0,%1}, [%2];"
        : "=r"(r[0]),"=r"(r[1]) : "r"(addr));
}
#define AROW(lane) (((lane)&7) + (((lane)>>3)&1)*8)
#define ACOL(lane) (((lane)>>4)*8)
#define BROW(lane) (((lane)&7) + (((lane)>>4)&1)*8)
#define BCOL(lane) ((((lane)>>3)&1)*8)

// ---------------------------------------------------------------------------
// fused fp32 -> fp16 split kernels
// ---------------------------------------------------------------------------
__global__ __launch_bounds__(256) void split_act(
    const float* __restrict__ q, const float* __restrict__ k,
    const float* __restrict__ v, h16* __restrict__ base)
{
    const float* x = (blockIdx.y == 0) ? q : (blockIdx.y == 1) ? k : v;
    h16* hi = base + (size_t)blockIdx.y * CHK;
    int i = (blockIdx.x * 256 + threadIdx.x) * 4;
    float4 w = *(const float4*)(x + i);
    *(uint2*)(hi + i) = make_uint2(pkf(w.x, w.y), pkf(w.z, w.w));
}
__global__ __launch_bounds__(256) void split_w(
    const float* __restrict__ w0, const float* __restrict__ w1,
    const float* __restrict__ w2, const float* __restrict__ w3,
    h16* __restrict__ base)
{
    const float* x = (blockIdx.y == 0) ? w0 : (blockIdx.y == 1) ? w1
                   : (blockIdx.y == 2) ? w2 : w3;
    h16* hi = base + (size_t)(2*blockIdx.y    ) * WCH;
    h16* lo = base + (size_t)(2*blockIdx.y + 1) * WCH;
    int i = (blockIdx.x * 256 + threadIdx.x) * 4;
    float4 v = *(const float4*)(x + i);
    h16 h0,l0,h1,l1,h2,l2,h3,l3;
    hsplit(v.x,h0,l0); hsplit(v.y,h1,l1); hsplit(v.z,h2,l2); hsplit(v.w,h3,l3);
    *(uint2*)(hi + i) = make_uint2(pkh(h0,h1), pkh(h2,h3));
    *(uint2*)(lo + i) = make_uint2(pkh(l0,l1), pkh(l2,l3));
}

__global__ __launch_bounds__(256) void maskpack_kernel(const int* __restrict__ mask)
{
    int i = blockIdx.x * 256 + threadIdx.x;
    unsigned w = __ballot_sync(0xffffffffu, mask[i] != 0);
    if ((threadIdx.x & 31) == 0) g_mbits[i >> 5] = w;
}

// ---------------------------------------------------------------------------
// C = A[M,K] @ W[N,K]^T, fp16. comp=1: one-sided W compensation.
// CTA 128(M) x 64(N), k-tile 32, 256 thr = 8 warps (4m x 2n), warp 32x32.
// mode 0: fp32 flat  1: hi-only [BH,S,DH]  2: hi+lo [BH,S,DH]  3: hi T [BH,DH,S]
// ---------------------------------------------------------------------------
__global__ __launch_bounds__(256) void proj_mma(
    const h16* __restrict__ Ah_g,
    const h16* __restrict__ Wh_g, const h16* __restrict__ Wl_g,
    float* __restrict__ Cf, h16* __restrict__ Ch, h16* __restrict__ Cl,
    int mode, int comp)
{
    __shared__ h16 As[2][128][40];
    __shared__ h16 Ws[2][2][64][40];

    const int tid = threadIdx.x, lane = tid & 31, wid = tid >> 5;
    const int wm = wid >> 1, wn = wid & 1;
    const int g = lane >> 2, t = lane & 3;
    const int m0 = blockIdx.y * 128, n0 = blockIdx.x * 64;

    const uns as_a = smem_u32(&As[0][0][0]);
    const uns ws_a = smem_u32(&Ws[0][0][0][0]);
    const int arow = AROW(lane), acol = ACOL(lane);
    const int brow = BROW(lane), bcol = BCOL(lane);

    float acc[2][4][4];
    #pragma unroll
    for (int i=0;i<2;i++)
        #pragma unroll
        for (int j=0;j<4;j++)
            #pragma unroll
            for (int e=0;e<4;e++) acc[i][j][e]=0.f;

    auto pre = [&](int kt, int s){
        const int k0 = kt * 32;
        #pragma unroll
        for (int i = 0; i < 2; i++){
            int idx = tid + i*256;
            int r = idx >> 2, c = idx & 3;
            CP16(smem_u32(&As[s][r][c*8]), Ah_g + (size_t)(m0+r)*DD + k0 + c*8);
        }
        if (comp){
            #pragma unroll
            for (int i = 0; i < 2; i++){
                int idx = tid + i*256;
                int pl = idx >> 8, rem = idx & 255;
                int r = rem >> 2, c = rem & 3;
                CP16(smem_u32(&Ws[pl][s][r][c*8]),
                     (pl ? Wl_g : Wh_g) + (size_t)(n0+r)*DD + k0 + c*8);
            }
        } else {
            int r = tid >> 2, c = tid & 3;
            CP16(smem_u32(&Ws[0][s][r][c*8]),
                 Wh_g + (size_t)(n0+r)*DD + k0 + c*8);
        }
        CPCOMMIT();
    };

    pre(0, 0);
    const int NT = DD / 32;   // 32
    for (int kt = 0; kt < NT; kt++){
        const int s = kt & 1;
        if (kt + 1 < NT){ pre(kt + 1, s ^ 1); CPWAIT(1); }
        else            { CPWAIT(0); }
        __syncthreads();

        #pragma unroll
        for (int ks = 0; ks < 2; ks++){
            const int k0 = ks*16;
            uns ah[2][4];
            #pragma unroll
            for (int mt = 0; mt < 2; mt++)
                ldm4(ah[mt], as_a + ((s*128 + wm*32 + mt*16 + arow)*40
                                     + k0 + acol)*2);
            uns bhq[2][4], blq[2][4];
            #pragma unroll
            for (int hq = 0; hq < 2; hq++){
                ldm4(bhq[hq], ws_a + (((0*2+s)*64 + wn*32 + hq*16 + brow)*40
                                      + k0 + bcol)*2);
                if (comp)
                    ldm4(blq[hq], ws_a + (((1*2+s)*64 + wn*32 + hq*16 + brow)*40
                                          + k0 + bcol)*2);
            }
            #pragma unroll
            for (int mt = 0; mt < 2; mt++)
                #pragma unroll
                for (int nt = 0; nt < 4; nt++){
                    const int hq = nt >> 1, p = (nt & 1) * 2;
                    mma_f16(acc[mt][nt], ah[mt], bhq[hq][p], bhq[hq][p+1]);
                    if (comp)
                        mma_f16(acc[mt][nt], ah[mt], blq[hq][p], blq[hq][p+1]);
                }
        }
        __syncthreads();
    }

    if (mode == 0){
        #pragma unroll
        for (int mt = 0; mt < 2; mt++)
            #pragma unroll
            for (int nt = 0; nt < 4; nt++){
                const int r0 = m0 + wm*32 + mt*16 + g;
                const int r1 = r0 + 8;
                const int cb = n0 + wn*32 + nt*8 + 2*t;
                float* a = acc[mt][nt];
                *(float2*)&Cf[(size_t)r0*DD + cb] = make_float2(a[0], a[1]);
                *(float2*)&Cf[(size_t)r1*DD + cb] = make_float2(a[2], a[3]);
            }
        return;
    }

    const int b = m0 >> 11, sq0 = m0 & (SS-1), h = n0 >> 6;

    if (mode == 1 || mode == 2){
        h16* sh_ = (h16*)As;   // [128][72]
        h16* sl_ = (h16*)Ws;
        #pragma unroll
        for (int mt = 0; mt < 2; mt++)
            #pragma unroll
            for (int nt = 0; nt < 4; nt++){
                const int dhl = wn*32 + nt*8 + 2*t;
                const int ml0 = wm*32 + mt*16 + g;
                float* a = acc[mt][nt];
                if (mode == 1){
                    *(uns*)&sh_[(ml0    )*72 + dhl] = pkf(a[0], a[1]);
                    *(uns*)&sh_[(ml0 + 8)*72 + dhl] = pkf(a[2], a[3]);
                } else {
                    h16 h0,l0,h1,l1;
                    hsplit(a[0],h0,l0); hsplit(a[1],h1,l1);
                    *(uns*)&sh_[(ml0)*72 + dhl] = pkh(h0,h1);
                    *(uns*)&sl_[(ml0)*72 + dhl] = pkh(l0,l1);
                    hsplit(a[2],h0,l0); hsplit(a[3],h1,l1);
                    *(uns*)&sh_[(ml0+8)*72 + dhl] = pkh(h0,h1);
                    *(uns*)&sl_[(ml0+8)*72 + dhl] = pkh(l0,l1);
                }
            }
        __syncthreads();
        #pragma unroll
        for (int i = 0; i < 4; i++){
            int idx = tid + i*256;
            int r = idx >> 3, c = idx & 7;
            size_t base = ((size_t)(b*HH + h)*SS + sq0 + r)*DH + c*8;
            *(uint4*)&Ch[base] = *(uint4*)&sh_[r*72 + c*8];
            if (mode == 2)
                *(uint4*)&Cl[base] = *(uint4*)&sl_[r*72 + c*8];
        }
    } else {  // mode 3: transposed hi-only [BH,DH,S]
        h16* stg = (h16*)As;   // [64][136]
        #pragma unroll
        for (int mt = 0; mt < 2; mt++)
            #pragma unroll
            for (int nt = 0; nt < 4; nt++){
                float* a = acc[mt][nt];
                #pragma unroll
                for (int e = 0; e < 4; e++){
                    int dh = wn*32 + nt*8 + 2*t + (e & 1);
                    int ml = wm*32 + mt*16 + g + ((e < 2) ? 0 : 8);
                    stg[dh*136 + ml] = __float2half_rn(a[e]);
                }
            }
        __syncthreads();
        #pragma unroll
        for (int i = 0; i < 4; i++){
            int idx = tid + i*256;
            int r = idx >> 4, c = idx & 15;
            *(uint4*)&Ch[((size_t)(b*HH + h)*DH + r)*SS + sq0 + c*8]
                = *(uint4*)&stg[r*136 + c*8];
        }
    }
}

// ---------------------------------------------------------------------------
// FUSED scores + mask + softmax + ctx. 256 threads (R12-proven core).
// Phase 1: S = QK^T/8, mask, running max (ps fp32 in smem).
// Phase 2: softmax (exp writeback + sums), write attn fp32, write P fp16
//          into the freed K smem region.
// Phase 3: ctx tile = P @ V^T streamed from global (V hi-only), staged write.
// dyn smem layout (bytes):
//   [0,131328)        ps [16][2052] f32     | phase3: V tiles [2][64][136] h16
//   [131328,133632)   qsm [16][72] h16      | phase3: ctx out stage [16][72]
//   [133632,207360)   ksm [2][2][128][72]   | phase2+: p16s [16][2056] h16
//   [207360,207424)   invs[16]
//   [207424,207936)   wmax[16][8]
// ---------------------------------------------------------------------------
#define SC_SMEM 207936

__global__ __launch_bounds__(256) void scores_ctx(
    const h16* __restrict__ Qh_g,
    const h16* __restrict__ Kh_g, const h16* __restrict__ Kl_g,
    const h16* __restrict__ Vt_g,
    float* __restrict__ attn, h16* __restrict__ Ch)
{
    extern __shared__ __align__(16) unsigned char dynsm[];
    float* ps  = (float*)dynsm;
    h16* qsm   = (h16*)(dynsm + 131328);
    h16* ksm   = (h16*)(dynsm + 133632);
    float* invs= (float*)(dynsm + 207360);
    float* wmax= (float*)(dynsm + 207424);
    h16* vsm   = (h16*)dynsm;              // phase3 alias
    h16* p16s  = (h16*)(dynsm + 133632);   // phase2+ alias
    h16* stg   = qsm;                      // phase3 out stage

    const int tid = threadIdx.x, lane = tid & 31, wid = tid >> 5;
    const int g = lane >> 2, t = lane & 3;
    const int bh = blockIdx.y, q0 = blockIdx.x * 16;

    const uns q_a = smem_u32(qsm);
    const uns k_a = smem_u32(ksm);
    const uns v_a = smem_u32(vsm);
    const uns p_a = smem_u32(p16s);
    const int arow = AROW(lane), acol = ACOL(lane);
    const int brow = BROW(lane), bcol = BCOL(lane);
    const int b2row = lane & 7, b2col = ((lane >> 3) & 1) * 8;

    // stage Q tile (16x64 hi)
    if (tid < 128){
        int r = tid >> 3, c = tid & 7;
        CP16(smem_u32(qsm + r*72 + c*8),
             Qh_g + ((size_t)bh*SS + q0 + r)*DH + c*8);
    }

    auto preK = [&](int kb, int s){
        #pragma unroll
        for (int i = 0; i < 8; i++){
            int idx = tid + i*256;
            int pl = idx >> 10, j = idx & 1023;
            int r = j >> 3, c = j & 7;
            const h16* src = (pl ? Kl_g : Kh_g)
                           + ((size_t)bh*SS + kb*128 + r)*DH + c*8;
            CP16(smem_u32(ksm + ((s*2+pl)*128 + r)*72 + c*8), src);
        }
        CPCOMMIT();
    };

    preK(0, 0);

    uns qa[4][4];
    const int nbase = wid * 16;
    float mr0 = -3.0e38f, mr8 = -3.0e38f;

    // ---------------- phase 1: scores ----------------
    for (int kb = 0; kb < 16; kb++){
        const int s = kb & 1;
        if (kb + 1 < 16){ preK(kb + 1, s ^ 1); CPWAIT(1); }
        else            { CPWAIT(0); }
        __syncthreads();

        if (kb == 0){
            #pragma unroll
            for (int ck = 0; ck < 4; ck++)
                ldm4(qa[ck], q_a + (arow*72 + ck*16 + acol)*2);
        }

        float acc[2][4] = {{0.f,0.f,0.f,0.f},{0.f,0.f,0.f,0.f}};
        #pragma unroll
        for (int ck = 0; ck < 4; ck++){
            uns bh2[4], bl2[4];
            ldm4(bh2, k_a + (((s*2+0)*128 + nbase + brow)*72 + ck*16 + bcol)*2);
            ldm4(bl2, k_a + (((s*2+1)*128 + nbase + brow)*72 + ck*16 + bcol)*2);
            mma_f16(acc[0], qa[ck], bh2[0], bh2[1]);
            mma_f16(acc[0], qa[ck], bl2[0], bl2[1]);
            mma_f16(acc[1], qa[ck], bh2[2], bh2[3]);
            mma_f16(acc[1], qa[ck], bl2[2], bl2[3]);
        }

        #pragma unroll
        for (int nt = 0; nt < 2; nt++){
            const int col = kb*128 + nbase + nt*8 + 2*t;
            const unsigned w0 = g_mbits[((size_t)(q0 + g    )*SS + col) >> 5];
            const unsigned w8 = g_mbits[((size_t)(q0 + g + 8)*SS + col) >> 5];
            const int sh = col & 31;
            float s0 = ((w0 >> sh)     & 1) ? acc[nt][0]*0.125f : -1e34f;
            float s1 = ((w0 >> (sh+1)) & 1) ? acc[nt][1]*0.125f : -1e34f;
            float s2 = ((w8 >> sh)     & 1) ? acc[nt][2]*0.125f : -1e34f;
            float s3 = ((w8 >> (sh+1)) & 1) ? acc[nt][3]*0.125f : -1e34f;
            ps[(g    )*2052 + col    ] = s0;
            ps[(g    )*2052 + col + 1] = s1;
            ps[(g + 8)*2052 + col    ] = s2;
            ps[(g + 8)*2052 + col + 1] = s3;
            mr0 = fmaxf(mr0, fmaxf(s0, s1));
            mr8 = fmaxf(mr8, fmaxf(s2, s3));
        }
        __syncthreads();
    }

    // ---------------- phase 2: softmax + writes ----------------
    #pragma unroll
    for (int off = 1; off < 4; off <<= 1){
        mr0 = fmaxf(mr0, __shfl_xor_sync(0xffffffffu, mr0, off));
        mr8 = fmaxf(mr8, __shfl_xor_sync(0xffffffffu, mr8, off));
    }
    if (t == 0){
        wmax[(g    )*8 + wid] = mr0;
        wmax[(g + 8)*8 + wid] = mr8;
    }
    __syncthreads();

    {
        const int row = tid >> 4, sub = tid & 15;
        float* pr = ps + row * 2052;
        float mx = -3.0e38f;
        #pragma unroll
        for (int j = 0; j < 8; j++) mx = fmaxf(mx, wmax[row*8 + j]);
        float sum = 0.f;
        for (int k2 = sub; k2 < SS; k2 += 16){
            float e = __expf(pr[k2] - mx);
            pr[k2] = e;
            sum += e;
        }
        #pragma unroll
        for (int off = 1; off < 16; off <<= 1)
            sum += __shfl_xor_sync(0xffffffffu, sum, off);
        if (sub == 0) invs[row] = 1.f / sum;
    }
    __syncthreads();

    // write attn (f32 global) + P fp16 into freed K smem region
    float* Ar = attn + ((size_t)bh * SS + q0) * SS;
    #pragma unroll
    for (int i = 0; i < 32; i++){
        int idx = tid + i * 256;
        int r = idx >> 9, c4 = idx & 511;
        float inv = invs[r];
        float4 v = *(float4*)&ps[r * 2052 + c4 * 4];
        v.x *= inv; v.y *= inv; v.z *= inv; v.w *= inv;
        *(float4*)&Ar[(size_t)r * SS + c4 * 4] = v;
        *(uint2*)&p16s[r * 2056 + c4 * 4] = make_uint2(pkf(v.x, v.y),
                                                       pkf(v.z, v.w));
    }
    __syncthreads();   // ps dead; p16s live

    // ---------------- phase 3: ctx = P @ V^T ----------------
    const h16* Vtb = Vt_g + (size_t)bh * DH * SS;

    auto preV = [&](int kt, int s){
        #pragma unroll
        for (int i = 0; i < 4; i++){          // 1024 chunks: 64 dh x 16 c
            int idx = tid + i*256;
            int r = idx >> 4, c = idx & 15;
            CP16(smem_u32(vsm + (s*64 + r)*136 + c*8),
                 Vtb + (size_t)r*SS + kt*128 + c*8);
        }
        CPCOMMIT();
    };

    preV(0, 0);
    const int nb = wid * 8;                  // 8 warps x 8 dh = 64
    float cacc[4] = {0.f, 0.f, 0.f, 0.f};

    for (int kt = 0; kt < 16; kt++){
        const int s = kt & 1;
        if (kt + 1 < 16){ preV(kt + 1, s ^ 1); CPWAIT(1); }
        else            { CPWAIT(0); }
        __syncthreads();

        #pragma unroll
        for (int ks = 0; ks < 8; ks++){
            const int k0 = kt*128 + ks*16;
            uns a4[4];
            ldm4(a4, p_a + (arow*2056 + k0 + acol)*2);
            uns b2[2];
            ldm2(b2, v_a + ((s*64 + nb + b2row)*136 + ks*16 + b2col)*2);
            mma_f16(cacc, a4, b2[0], b2[1]);
        }
        __syncthreads();
    }

    // staged coalesced ctx write
    *(uns*)&stg[(g    )*72 + nb + 2*t] = pkf(cacc[0], cacc[1]);
    *(uns*)&stg[(g + 8)*72 + nb + 2*t] = pkf(cacc[2], cacc[3]);
    __syncthreads();
    const int b = bh >> 4, h = bh & 15;
    if (tid < 128){
        int r = tid >> 3, c = tid & 7;
        *(uint4*)&Ch[((size_t)(b*SS + q0 + r))*DD + h*64 + c*8]
            = *(uint4*)&stg[r*72 + c*8];
    }
}

// ---------------------------------------------------------------------------
extern "C" void kernel_launch(void* const* d_in, const int* in_sizes, int n_in,
                              void* d_out, int out_size)
{
    const float* q    = (const float*)d_in[0];
    const float* k    = (const float*)d_in[1];
    const float* v    = (const float*)d_in[2];
    const int*   mask = (const int*)  d_in[3];
    const float* Wq   = (const float*)d_in[4];
    const float* Wk   = (const float*)d_in[5];
    const float* Wv   = (const float*)d_in[6];
    const float* Wo   = (const float*)d_in[7];

    float* out  = (float*)d_out;               // [B,S,D]
    float* attn = out + (size_t)MM * DD;       // [B,H,S,S]

    h16* P; cudaGetSymbolAddress((void**)&P, g_hf);
    h16 *xa_h = P + (size_t)0*CHK;
    h16 *xb_h = P + (size_t)1*CHK;
    h16 *xc_h = P + (size_t)2*CHK;
    h16 *qh_h = P + (size_t)3*CHK;
    h16 *kh_h = P + (size_t)4*CHK, *kh_l = P + (size_t)5*CHK;
    h16 *vt_h = P + (size_t)6*CHK;
    h16 *cx_h = P + (size_t)8*CHK;
    h16 *wb   = P + (size_t)9*CHK;
    h16 *wq_h = wb + (size_t)0*WCH, *wq_l = wb + (size_t)1*WCH;
    h16 *wk_h = wb + (size_t)2*WCH, *wk_l = wb + (size_t)3*WCH;
    h16 *wv_h = wb + (size_t)4*WCH;
    h16 *wo_h = wb + (size_t)6*WCH;

    cudaFuncSetAttribute(scores_ctx,
        cudaFuncAttributeMaxDynamicSharedMemorySize, SC_SMEM);

    split_act<<<dim3(MM*DD/1024, 3), 256>>>(q, k, v, P);
    split_w  <<<dim3(DD*DD/1024, 4), 256>>>(Wq, Wk, Wv, Wo, wb);
    maskpack_kernel<<<SS*SS/256, 256>>>(mask);

    dim3 gproj(DD / 64, MM / 128);   // (16, 32)

    proj_mma<<<gproj, 256>>>(xa_h, wq_h, wq_l, nullptr, qh_h, nullptr, 1, 1);
    proj_mma<<<gproj, 256>>>(xb_h, wk_h, wk_l, nullptr, kh_h, kh_l,   2, 1);
    proj_mma<<<gproj, 256>>>(xc_h, wv_h, nullptr, nullptr, vt_h, nullptr, 3, 0);

    scores_ctx<<<dim3(SS/16, BH), 256, SC_SMEM>>>(qh_h, kh_h, kh_l, vt_h,
                                                  attn, cx_h);

    proj_mma<<<gproj, 256>>>(cx_h, wo_h, nullptr, out, nullptr, nullptr, 0, 0);
}

// round 15
// speedup vs baseline: 1.2597x; 1.2597x over previous
#include <cuda_runtime.h>
#include <cuda_fp16.h>
#include <math.h>

// Problem constants
#define BB   2
#define SS   2048
#define DD   1024
#define HH   16
#define DH   64
#define MM   (BB*SS)     // 4096
#define BH   (BB*HH)     // 32

typedef __half h16;
typedef unsigned uns;

// ---------------------------------------------------------------------------
// Scratch arena (device globals: allocation-free)
// ---------------------------------------------------------------------------
#define CHK (1u<<22)
#define WCH (1u<<20)
__device__ h16 g_hf[(size_t)9*CHK + 8*WCH];
__device__ h16 g_p16[(size_t)BH*SS*SS];          // fp16 probabilities
__device__ unsigned g_mbits[(size_t)SS*SS/32];

// ---------------------------------------------------------------------------
// helpers
// ---------------------------------------------------------------------------
__device__ __forceinline__ unsigned smem_u32(const void* p){
    unsigned r;
    asm("{ .reg .u64 t; cvta.to.shared.u64 t, %1; cvt.u32.u64 %0, t; }"
        : "=r"(r) : "l"(p));
    return r;
}
#define CP16(dst,src) asm volatile("cp.async.cg.shared.global [%0], [%1], 16;\n" :: "r"(dst), "l"(src))
#define CPCOMMIT()    asm volatile("cp.async.commit_group;\n")
#define CPWAIT(N)     asm volatile("cp.async.wait_group %0;\n" :: "n"(N))

__device__ __forceinline__ uns pkf(float a, float b){
    __half2 t = __floats2half2_rn(a, b);
    return *(uns*)&t;
}
__device__ __forceinline__ uns pkh(h16 a, h16 b){
    return (uns)__half_as_ushort(a) | ((uns)__half_as_ushort(b) << 16);
}
__device__ __forceinline__ void hsplit(float x, h16 &h, h16 &l){
    h = __float2half_rn(x);
    l = __float2half_rn(x - __half2float(h));
}

__device__ __forceinline__ void mma_f16(float c[4], const uns a[4], const uns b0, const uns b1){
    asm volatile("mma.sync.aligned.m16n8k16.row.col.f32.f16.f16.f32 "
        "{%0,%1,%2,%3}, {%4,%5,%6,%7}, {%8,%9}, {%0,%1,%2,%3};"
        : "+f"(c[0]),"+f"(c[1]),"+f"(c[2]),"+f"(c[3])
        : "r"(a[0]),"r"(a[1]),"r"(a[2]),"r"(a[3]),"r"(b0),"r"(b1));
}
__device__ __forceinline__ void ldm4(uns r[4], uns addr){
    asm volatile("ldmatrix.sync.aligned.m8n8.x4.shared.b16 {%0,%1,%2,%3}, [%4];"
        : "=r"(r[0]),"=r"(r[1]),"=r"(r[2]),"=r"(r[3]) : "r"(addr));
}
#define AROW(lane) (((lane)&7) + (((lane)>>3)&1)*8)
#define ACOL(lane) (((lane)>>4)*8)
#define BROW(lane) (((lane)&7) + (((lane)>>4)&1)*8)
#define BCOL(lane) ((((lane)>>3)&1)*8)

// ---------------------------------------------------------------------------
// fused fp32 -> fp16 split kernels
// ---------------------------------------------------------------------------
__global__ __launch_bounds__(256) void split_act(
    const float* __restrict__ q, const float* __restrict__ k,
    const float* __restrict__ v, h16* __restrict__ base)
{
    const float* x = (blockIdx.y == 0) ? q : (blockIdx.y == 1) ? k : v;
    h16* hi = base + (size_t)blockIdx.y * CHK;
    int i = (blockIdx.x * 256 + threadIdx.x) * 4;
    float4 w = *(const float4*)(x + i);
    *(uint2*)(hi + i) = make_uint2(pkf(w.x, w.y), pkf(w.z, w.w));
}
__global__ __launch_bounds__(256) void split_w(
    const float* __restrict__ w0, const float* __restrict__ w1,
    const float* __restrict__ w2, const float* __restrict__ w3,
    h16* __restrict__ base)
{
    const float* x = (blockIdx.y == 0) ? w0 : (blockIdx.y == 1) ? w1
                   : (blockIdx.y == 2) ? w2 : w3;
    h16* hi = base + (size_t)(2*blockIdx.y    ) * WCH;
    h16* lo = base + (size_t)(2*blockIdx.y + 1) * WCH;
    int i = (blockIdx.x * 256 + threadIdx.x) * 4;
    float4 v = *(const float4*)(x + i);
    h16 h0,l0,h1,l1,h2,l2,h3,l3;
    hsplit(v.x,h0,l0); hsplit(v.y,h1,l1); hsplit(v.z,h2,l2); hsplit(v.w,h3,l3);
    *(uint2*)(hi + i) = make_uint2(pkh(h0,h1), pkh(h2,h3));
    *(uint2*)(lo + i) = make_uint2(pkh(l0,l1), pkh(l2,l3));
}

__global__ __launch_bounds__(256) void maskpack_kernel(const int* __restrict__ mask)
{
    int i = blockIdx.x * 256 + threadIdx.x;
    unsigned w = __ballot_sync(0xffffffffu, mask[i] != 0);
    if ((threadIdx.x & 31) == 0) g_mbits[i >> 5] = w;
}

// ---------------------------------------------------------------------------
// C = A[M,K] @ W[N,K]^T, fp16. comp=1: one-sided W compensation (2 MMA/k16);
// comp=0: plain fp16. ldmatrix frag loads.
// CTA 128(M) x 64(N), k-tile 32, 256 thr = 8 warps (4m x 2n), warp 32x32.
// mode 0: fp32 flat  1: hi-only [BH,S,DH]  2: hi+lo [BH,S,DH]  3: hi T [BH,DH,S]
// ---------------------------------------------------------------------------
__global__ __launch_bounds__(256) void proj_mma(
    const h16* __restrict__ Ah_g,
    const h16* __restrict__ Wh_g, const h16* __restrict__ Wl_g,
    float* __restrict__ Cf, h16* __restrict__ Ch, h16* __restrict__ Cl,
    int mode, int comp)
{
    __shared__ h16 As[2][128][40];
    __shared__ h16 Ws[2][2][64][40];   // [pl][stage]

    const int tid = threadIdx.x, lane = tid & 31, wid = tid >> 5;
    const int wm = wid >> 1, wn = wid & 1;
    const int g = lane >> 2, t = lane & 3;
    const int m0 = blockIdx.y * 128, n0 = blockIdx.x * 64;

    const uns as_a = smem_u32(&As[0][0][0]);
    const uns ws_a = smem_u32(&Ws[0][0][0][0]);
    const int arow = AROW(lane), acol = ACOL(lane);
    const int brow = BROW(lane), bcol = BCOL(lane);

    float acc[2][4][4];
    #pragma unroll
    for (int i=0;i<2;i++)
        #pragma unroll
        for (int j=0;j<4;j++)
            #pragma unroll
            for (int e=0;e<4;e++) acc[i][j][e]=0.f;

    auto pre = [&](int kt, int s){
        const int k0 = kt * 32;
        #pragma unroll
        for (int i = 0; i < 2; i++){
            int idx = tid + i*256;
            int r = idx >> 2, c = idx & 3;
            CP16(smem_u32(&As[s][r][c*8]), Ah_g + (size_t)(m0+r)*DD + k0 + c*8);
        }
        if (comp){
            #pragma unroll
            for (int i = 0; i < 2; i++){
                int idx = tid + i*256;
                int pl = idx >> 8, rem = idx & 255;
                int r = rem >> 2, c = rem & 3;
                CP16(smem_u32(&Ws[pl][s][r][c*8]),
                     (pl ? Wl_g : Wh_g) + (size_t)(n0+r)*DD + k0 + c*8);
            }
        } else {
            int r = tid >> 2, c = tid & 3;
            CP16(smem_u32(&Ws[0][s][r][c*8]),
                 Wh_g + (size_t)(n0+r)*DD + k0 + c*8);
        }
        CPCOMMIT();
    };

    pre(0, 0);
    const int NT = DD / 32;   // 32
    for (int kt = 0; kt < NT; kt++){
        const int s = kt & 1;
        if (kt + 1 < NT){ pre(kt + 1, s ^ 1); CPWAIT(1); }
        else            { CPWAIT(0); }
        __syncthreads();

        #pragma unroll
        for (int ks = 0; ks < 2; ks++){
            const int k0 = ks*16;
            uns ah[2][4];
            #pragma unroll
            for (int mt = 0; mt < 2; mt++)
                ldm4(ah[mt], as_a + ((s*128 + wm*32 + mt*16 + arow)*40
                                     + k0 + acol)*2);
            uns bhq[2][4], blq[2][4];
            #pragma unroll
            for (int hq = 0; hq < 2; hq++){
                ldm4(bhq[hq], ws_a + (((0*2+s)*64 + wn*32 + hq*16 + brow)*40
                                      + k0 + bcol)*2);
                if (comp)
                    ldm4(blq[hq], ws_a + (((1*2+s)*64 + wn*32 + hq*16 + brow)*40
                                          + k0 + bcol)*2);
            }
            #pragma unroll
            for (int mt = 0; mt < 2; mt++)
                #pragma unroll
                for (int nt = 0; nt < 4; nt++){
                    const int hq = nt >> 1, p = (nt & 1) * 2;
                    mma_f16(acc[mt][nt], ah[mt], bhq[hq][p], bhq[hq][p+1]);
                    if (comp)
                        mma_f16(acc[mt][nt], ah[mt], blq[hq][p], blq[hq][p+1]);
                }
        }
        __syncthreads();
    }

    #pragma unroll
    for (int mt = 0; mt < 2; mt++){
        #pragma unroll
        for (int nt = 0; nt < 4; nt++){
            const int r0 = m0 + wm*32 + mt*16 + g;
            const int r1 = r0 + 8;
            const int cb = n0 + wn*32 + nt*8 + 2*t;
            float* a = acc[mt][nt];
            if (mode == 0){
                *(float2*)&Cf[(size_t)r0*DD + cb] = make_float2(a[0], a[1]);
                *(float2*)&Cf[(size_t)r1*DD + cb] = make_float2(a[2], a[3]);
            } else if (mode == 1 || mode == 2){
                const int h = cb >> 6, dh = cb & 63;
                #pragma unroll
                for (int p = 0; p < 2; p++){
                    int m = p ? r1 : r0;
                    int b = m >> 11, sq = m & (SS - 1);
                    size_t base = (((size_t)(b*HH + h))*SS + sq)*DH + dh;
                    float x0 = a[p*2], x1 = a[p*2+1];
                    if (mode == 1){
                        *(uns*)&Ch[base] = pkf(x0, x1);
                    } else {
                        h16 h0,l0,h1,l1;
                        hsplit(x0,h0,l0); hsplit(x1,h1,l1);
                        *(uns*)&Ch[base] = pkh(h0,h1);
                        *(uns*)&Cl[base] = pkh(l0,l1);
                    }
                }
            } else {   // mode 3: hi-only transposed [BH,DH,S]
                #pragma unroll
                for (int e = 0; e < 4; e++){
                    int m = (e < 2) ? r0 : r1;
                    int n = cb + (e & 1);
                    int b = m >> 11, sq = m & (SS - 1);
                    int h = n >> 6, dh = n & 63;
                    size_t idx = (((size_t)(b*HH + h))*DH + dh)*SS + sq;
                    Ch[idx] = __float2half_rn(a[e]);
                }
            }
        }
    }
}

// ---------------------------------------------------------------------------
// Fused scores + mask + softmax. Q hi-only, K hi-only (plain fp16 QK^T).
// Mask+row-max folded into MMA epilogue. Emits attn (fp32) + p16 (fp16).
// dyn smem: ps[16][2052]f32 + q[16][72]h + k[2st][128][72]h
//           + invs[16] + wmax[16][8] = 171072 B
// ---------------------------------------------------------------------------
#define SC_SMEM (16*2052*4 + 16*72*2 + 2*128*72*2 + 64 + 512)

__global__ __launch_bounds__(256) void scores_softmax(
    const h16* __restrict__ Qh_g,
    const h16* __restrict__ Kh_g,
    float* __restrict__ attn, h16* __restrict__ p16)
{
    extern __shared__ __align__(16) unsigned char dynsm[];
    float* ps  = (float*)dynsm;
    h16* qsm   = (h16*)(dynsm + 16*2052*4);
    h16* ksm   = (h16*)(dynsm + 16*2052*4 + 16*72*2);
    float* invs= (float*)(dynsm + 16*2052*4 + 16*72*2 + 2*128*72*2);
    float* wmax= invs + 16;                       // [16][8]

    const int tid = threadIdx.x, lane = tid & 31, wid = tid >> 5;
    const int g = lane >> 2, t = lane & 3;
    const int bh = blockIdx.y, q0 = blockIdx.x * 16;

    const uns q_a = smem_u32(qsm);
    const uns k_a = smem_u32(ksm);
    const int arow = AROW(lane), acol = ACOL(lane);
    const int brow = BROW(lane), bcol = BCOL(lane);

    // stage Q tile hi plane (16x64): 128 chunks
    if (tid < 128){
        int r = tid >> 3, c = tid & 7;
        CP16(smem_u32(qsm + r*72 + c*8),
             Qh_g + ((size_t)bh*SS + q0 + r)*DH + c*8);
    }

    auto preK = [&](int kb, int s){
        #pragma unroll
        for (int i = 0; i < 4; i++){      // 1024 chunks (128r x 8c), hi only
            int idx = tid + i*256;
            int r = idx >> 3, c = idx & 7;
            CP16(smem_u32(ksm + (s*128 + r)*72 + c*8),
                 Kh_g + ((size_t)bh*SS + kb*128 + r)*DH + c*8);
        }
        CPCOMMIT();
    };

    preK(0, 0);

    uns qa[4][4];
    const int nbase = wid * 16;
    float mr0 = -3.0e38f, mr8 = -3.0e38f;

    for (int kb = 0; kb < 16; kb++){
        const int s = kb & 1;
        if (kb + 1 < 16){ preK(kb + 1, s ^ 1); CPWAIT(1); }
        else            { CPWAIT(0); }
        __syncthreads();

        if (kb == 0){
            #pragma unroll
            for (int ck = 0; ck < 4; ck++)
                ldm4(qa[ck], q_a + (arow*72 + ck*16 + acol)*2);
        }

        float acc[2][4] = {{0.f,0.f,0.f,0.f},{0.f,0.f,0.f,0.f}};
        #pragma unroll
        for (int ck = 0; ck < 4; ck++){
            uns bh2[4];
            ldm4(bh2, k_a + ((s*128 + nbase + brow)*72 + ck*16 + bcol)*2);
            mma_f16(acc[0], qa[ck], bh2[0], bh2[1]);
            mma_f16(acc[1], qa[ck], bh2[2], bh2[3]);
        }

        // scale + mask + ps write + running max
        #pragma unroll
        for (int nt = 0; nt < 2; nt++){
            const int col = kb*128 + nbase + nt*8 + 2*t;
            const unsigned w0 = g_mbits[((size_t)(q0 + g    )*SS + col) >> 5];
            const unsigned w8 = g_mbits[((size_t)(q0 + g + 8)*SS + col) >> 5];
            const int sh = col & 31;
            float s0 = ((w0 >> sh)     & 1) ? acc[nt][0]*0.125f : -1e34f;
            float s1 = ((w0 >> (sh+1)) & 1) ? acc[nt][1]*0.125f : -1e34f;
            float s2 = ((w8 >> sh)     & 1) ? acc[nt][2]*0.125f : -1e34f;
            float s3 = ((w8 >> (sh+1)) & 1) ? acc[nt][3]*0.125f : -1e34f;
            ps[(g    )*2052 + col    ] = s0;
            ps[(g    )*2052 + col + 1] = s1;
            ps[(g + 8)*2052 + col    ] = s2;
            ps[(g + 8)*2052 + col + 1] = s3;
            mr0 = fmaxf(mr0, fmaxf(s0, s1));
            mr8 = fmaxf(mr8, fmaxf(s2, s3));
        }
        __syncthreads();
    }

    #pragma unroll
    for (int off = 1; off < 4; off <<= 1){
        mr0 = fmaxf(mr0, __shfl_xor_sync(0xffffffffu, mr0, off));
        mr8 = fmaxf(mr8, __shfl_xor_sync(0xffffffffu, mr8, off));
    }
    if (t == 0){
        wmax[(g    )*8 + wid] = mr0;
        wmax[(g + 8)*8 + wid] = mr8;
    }
    __syncthreads();

    // softmax: 16 threads per row
    const int row = tid >> 4, sub = tid & 15;
    float* pr = ps + row * 2052;

    float mx = -3.0e38f;
    #pragma unroll
    for (int j = 0; j < 8; j++) mx = fmaxf(mx, wmax[row*8 + j]);

    float sum = 0.f;
    for (int k2 = sub; k2 < SS; k2 += 16){
        float e = __expf(pr[k2] - mx);
        pr[k2] = e;
        sum += e;
    }
    #pragma unroll
    for (int off = 1; off < 16; off <<= 1)
        sum += __shfl_xor_sync(0xffffffffu, sum, off);

    if (sub == 0) invs[row] = 1.f / sum;
    __syncthreads();

    // write attn (f32) + p16 (fp16)
    float* Ar = attn + ((size_t)bh * SS + q0) * SS;
    h16*   Pr = p16  + ((size_t)bh * SS + q0) * SS;
    #pragma unroll
    for (int i = 0; i < 32; i++){
        int idx = tid + i * 256;
        int r = idx >> 9, c4 = idx & 511;
        float inv = invs[r];
        float4 v = *(float4*)&ps[r * 2052 + c4 * 4];
        v.x *= inv; v.y *= inv; v.z *= inv; v.w *= inv;
        *(float4*)&Ar[(size_t)r * SS + c4 * 4] = v;
        *(uint2*)&Pr[(size_t)r * SS + c4 * 4] = make_uint2(pkf(v.x, v.y),
                                                           pkf(v.z, v.w));
    }
}

// ---------------------------------------------------------------------------
// ctx = P16 @ V (plain fp16: V hi only). ldmatrix frags, k-tile 64 keys.
// dyn smem: Ps[2][128][72]h + Vs[2][64][72]h = 55296 B
// ---------------------------------------------------------------------------
#define CTX_SMEM (2*128*72*2 + 2*64*72*2)

__global__ __launch_bounds__(256) void ctx_mma(
    const h16* __restrict__ P16,
    const h16* __restrict__ Vh_g,
    h16* __restrict__ Ch)
{
    extern __shared__ __align__(16) unsigned char dynsm[];
    h16* Psm = (h16*)dynsm;                    // [2][128][72]
    h16* Vsm = (h16*)(dynsm + 2*128*72*2);     // [2][64][72]

    const int tid = threadIdx.x, lane = tid & 31, wid = tid >> 5;
    const int wm = wid >> 1, wn = wid & 1;
    const int g = lane >> 2, t = lane & 3;
    const int bh = blockIdx.y, q0 = blockIdx.x * 128;

    const uns p_a = smem_u32(Psm);
    const uns v_a = smem_u32(Vsm);
    const int arow = AROW(lane), acol = ACOL(lane);
    const int brow = BROW(lane), bcol = BCOL(lane);

    const h16* Pb  = P16  + (size_t)bh * SS * SS;
    const h16* Vhb = Vh_g + (size_t)bh * DH * SS;

    float acc[2][4][4];
    #pragma unroll
    for (int i=0;i<2;i++)
        #pragma unroll
        for (int j=0;j<4;j++)
            #pragma unroll
            for (int e=0;e<4;e++) acc[i][j][e]=0.f;

    auto pre = [&](int kt, int s){
        const int k0 = kt * 64;
        #pragma unroll
        for (int i = 0; i < 4; i++){           // P: 1024 chunks (128r x 8c)
            int idx = tid + i*256;
            int r = idx >> 3, c = idx & 7;
            CP16(smem_u32(Psm + (s*128 + r)*72 + c*8),
                 Pb + (size_t)(q0 + r)*SS + k0 + c*8);
        }
        #pragma unroll
        for (int i = 0; i < 2; i++){           // V: 512 chunks (64r x 8c)
            int idx = tid + i*256;
            int r = idx >> 3, c = idx & 7;
            CP16(smem_u32(Vsm + (s*64 + r)*72 + c*8),
                 Vhb + (size_t)r*SS + k0 + c*8);
        }
        CPCOMMIT();
    };

    pre(0, 0);
    const int NT = SS / 64;   // 32
    for (int kt = 0; kt < NT; kt++){
        const int s = kt & 1;
        if (kt + 1 < NT){ pre(kt + 1, s ^ 1); CPWAIT(1); }
        else            { CPWAIT(0); }
        __syncthreads();

        #pragma unroll
        for (int ks = 0; ks < 4; ks++){
            const int k0 = ks*16;
            uns ah[2][4];
            #pragma unroll
            for (int mt = 0; mt < 2; mt++)
                ldm4(ah[mt], p_a + ((s*128 + wm*32 + mt*16 + arow)*72
                                    + k0 + acol)*2);
            uns bhq[2][4];
            #pragma unroll
            for (int hq = 0; hq < 2; hq++)
                ldm4(bhq[hq], v_a + ((s*64 + wn*32 + hq*16 + brow)*72
                                     + k0 + bcol)*2);
            #pragma unroll
            for (int mt = 0; mt < 2; mt++)
                #pragma unroll
                for (int nt = 0; nt < 4; nt++){
                    const int hq = nt >> 1, p = (nt & 1) * 2;
                    mma_f16(acc[mt][nt], ah[mt], bhq[hq][p], bhq[hq][p+1]);
                }
        }
        __syncthreads();
    }

    const int b = bh >> 4, h = bh & 15;
    #pragma unroll
    for (int mt = 0; mt < 2; mt++){
        #pragma unroll
        for (int nt = 0; nt < 4; nt++){
            const int r0 = q0 + wm*32 + mt*16 + g;
            const int r1 = r0 + 8;
            const int cb = h*64 + wn*32 + nt*8 + 2*t;
            float* a = acc[mt][nt];
            *(uns*)&Ch[(size_t)(b*SS + r0)*DD + cb] = pkf(a[0], a[1]);
            *(uns*)&Ch[(size_t)(b*SS + r1)*DD + cb] = pkf(a[2], a[3]);
        }
    }
}

// ---------------------------------------------------------------------------
extern "C" void kernel_launch(void* const* d_in, const int* in_sizes, int n_in,
                              void* d_out, int out_size)
{
    const float* q    = (const float*)d_in[0];
    const float* k    = (const float*)d_in[1];
    const float* v    = (const float*)d_in[2];
    const int*   mask = (const int*)  d_in[3];
    const float* Wq   = (const float*)d_in[4];
    const float* Wk   = (const float*)d_in[5];
    const float* Wv   = (const float*)d_in[6];
    const float* Wo   = (const float*)d_in[7];

    float* out  = (float*)d_out;               // [B,S,D]
    float* attn = out + (size_t)MM * DD;       // [B,H,S,S]

    h16* P; cudaGetSymbolAddress((void**)&P, g_hf);
    h16* p16; cudaGetSymbolAddress((void**)&p16, g_p16);
    h16 *xa_h = P + (size_t)0*CHK;
    h16 *xb_h = P + (size_t)1*CHK;
    h16 *xc_h = P + (size_t)2*CHK;
    h16 *qh_h = P + (size_t)3*CHK;
    h16 *kh_h = P + (size_t)4*CHK;
    h16 *vt_h = P + (size_t)6*CHK;
    h16 *cx_h = P + (size_t)8*CHK;
    h16 *wb   = P + (size_t)9*CHK;
    h16 *wq_h = wb + (size_t)0*WCH, *wq_l = wb + (size_t)1*WCH;
    h16 *wk_h = wb + (size_t)2*WCH, *wk_l = wb + (size_t)3*WCH;
    h16 *wv_h = wb + (size_t)4*WCH;
    h16 *wo_h = wb + (size_t)6*WCH, *wo_l = wb + (size_t)7*WCH;

    cudaFuncSetAttribute(scores_softmax,
        cudaFuncAttributeMaxDynamicSharedMemorySize, SC_SMEM);
    cudaFuncSetAttribute(ctx_mma,
        cudaFuncAttributeMaxDynamicSharedMemorySize, CTX_SMEM);

    split_act<<<dim3(MM*DD/1024, 3), 256>>>(q, k, v, P);
    split_w  <<<dim3(DD*DD/1024, 4), 256>>>(Wq, Wk, Wv, Wo, wb);
    maskpack_kernel<<<SS*SS/256, 256>>>(mask);

    dim3 gproj(DD / 64, MM / 128);   // (16, 32)

    proj_mma<<<gproj, 256>>>(xa_h, wq_h, wq_l, nullptr, qh_h, nullptr, 1, 1);
    proj_mma<<<gproj, 256>>>(xb_h, wk_h, wk_l, nullptr, kh_h, nullptr, 1, 1);

    scores_softmax<<<dim3(SS/16, BH), 256, SC_SMEM>>>(qh_h, kh_h, attn, p16);

    proj_mma<<<gproj, 256>>>(xc_h, wv_h, nullptr, nullptr, vt_h, nullptr, 3, 0);

    ctx_mma<<<dim3(SS/128, BH), 256, CTX_SMEM>>>(p16, vt_h, cx_h);

    proj_mma<<<gproj, 256>>>(cx_h, wo_h, wo_l, out, nullptr, nullptr, 0, 1);
}

// round 16
// speedup vs baseline: 1.3669x; 1.0851x over previous
#include <cuda_runtime.h>
#include <cuda_fp16.h>
#include <math.h>

// Problem constants
#define BB   2
#define SS   2048
#define DD   1024
#define HH   16
#define DH   64
#define MM   (BB*SS)     // 4096
#define BH   (BB*HH)     // 32

typedef __half h16;
typedef unsigned uns;

// ---------------------------------------------------------------------------
// Scratch arena (device globals: allocation-free)
// ---------------------------------------------------------------------------
#define CHK (1u<<22)
#define WCH (1u<<20)
__device__ h16 g_hf[(size_t)9*CHK + 8*WCH];
__device__ h16 g_p16[(size_t)BH*SS*SS];          // fp16 probabilities
__device__ unsigned g_mbits[(size_t)SS*SS/32];

// ---------------------------------------------------------------------------
// helpers
// ---------------------------------------------------------------------------
__device__ __forceinline__ unsigned smem_u32(const void* p){
    unsigned r;
    asm("{ .reg .u64 t; cvta.to.shared.u64 t, %1; cvt.u32.u64 %0, t; }"
        : "=r"(r) : "l"(p));
    return r;
}
#define CP16(dst,src) asm volatile("cp.async.cg.shared.global [%0], [%1], 16;\n" :: "r"(dst), "l"(src))
#define CPCOMMIT()    asm volatile("cp.async.commit_group;\n")
#define CPWAIT(N)     asm volatile("cp.async.wait_group %0;\n" :: "n"(N))

__device__ __forceinline__ uns pkf(float a, float b){
    __half2 t = __floats2half2_rn(a, b);
    return *(uns*)&t;
}
__device__ __forceinline__ uns pkh(h16 a, h16 b){
    return (uns)__half_as_ushort(a) | ((uns)__half_as_ushort(b) << 16);
}
__device__ __forceinline__ void hsplit(float x, h16 &h, h16 &l){
    h = __float2half_rn(x);
    l = __float2half_rn(x - __half2float(h));
}

__device__ __forceinline__ void mma_f16(float c[4], const uns a[4], const uns b0, const uns b1){
    asm volatile("mma.sync.aligned.m16n8k16.row.col.f32.f16.f16.f32 "
        "{%0,%1,%2,%3}, {%4,%5,%6,%7}, {%8,%9}, {%0,%1,%2,%3};"
        : "+f"(c[0]),"+f"(c[1]),"+f"(c[2]),"+f"(c[3])
        : "r"(a[0]),"r"(a[1]),"r"(a[2]),"r"(a[3]),"r"(b0),"r"(b1));
}
__device__ __forceinline__ void ldm4(uns r[4], uns addr){
    asm volatile("ldmatrix.sync.aligned.m8n8.x4.shared.b16 {%0,%1,%2,%3}, [%4];"
        : "=r"(r[0]),"=r"(r[1]),"=r"(r[2]),"=r"(r[3]) : "r"(addr));
}
#define AROW(lane) (((lane)&7) + (((lane)>>3)&1)*8)
#define ACOL(lane) (((lane)>>4)*8)
#define BROW(lane) (((lane)&7) + (((lane)>>4)&1)*8)
#define BCOL(lane) ((((lane)>>3)&1)*8)

// ---------------------------------------------------------------------------
// fused fp32 -> fp16 split kernels
// ---------------------------------------------------------------------------
__global__ __launch_bounds__(256) void split_act(
    const float* __restrict__ q, const float* __restrict__ k,
    const float* __restrict__ v, h16* __restrict__ base)
{
    const float* x = (blockIdx.y == 0) ? q : (blockIdx.y == 1) ? k : v;
    h16* hi = base + (size_t)blockIdx.y * CHK;
    int i = (blockIdx.x * 256 + threadIdx.x) * 4;
    float4 w = *(const float4*)(x + i);
    *(uint2*)(hi + i) = make_uint2(pkf(w.x, w.y), pkf(w.z, w.w));
}
__global__ __launch_bounds__(256) void split_w(
    const float* __restrict__ w0, const float* __restrict__ w1,
    const float* __restrict__ w2, const float* __restrict__ w3,
    h16* __restrict__ base)
{
    const float* x = (blockIdx.y == 0) ? w0 : (blockIdx.y == 1) ? w1
                   : (blockIdx.y == 2) ? w2 : w3;
    h16* hi = base + (size_t)(2*blockIdx.y    ) * WCH;
    h16* lo = base + (size_t)(2*blockIdx.y + 1) * WCH;
    int i = (blockIdx.x * 256 + threadIdx.x) * 4;
    float4 v = *(const float4*)(x + i);
    h16 h0,l0,h1,l1,h2,l2,h3,l3;
    hsplit(v.x,h0,l0); hsplit(v.y,h1,l1); hsplit(v.z,h2,l2); hsplit(v.w,h3,l3);
    *(uint2*)(hi + i) = make_uint2(pkh(h0,h1), pkh(h2,h3));
    *(uint2*)(lo + i) = make_uint2(pkh(l0,l1), pkh(l2,l3));
}

__global__ __launch_bounds__(256) void maskpack_kernel(const int* __restrict__ mask)
{
    int i = blockIdx.x * 256 + threadIdx.x;
    unsigned w = __ballot_sync(0xffffffffu, mask[i] != 0);
    if ((threadIdx.x & 31) == 0) g_mbits[i >> 5] = w;
}

// ---------------------------------------------------------------------------
// C = A[M,K] @ W[N,K]^T, fp16. comp=1: one-sided W compensation.
// 3-stage cp.async pipeline, ONE barrier per k-tile.
// CTA 128(M) x 64(N), k-tile 32, 256 thr = 8 warps (4m x 2n), warp 32x32.
// dyn smem: sA[3][128][40] + sW[2pl][3][64][40] h16 = 61440 B
// mode 0: fp32 flat  1: hi-only [BH,S,DH]  2: hi+lo [BH,S,DH]  3: hi T [BH,DH,S]
// ---------------------------------------------------------------------------
#define PROJ_SMEM 61440

__global__ __launch_bounds__(256) void proj_mma(
    const h16* __restrict__ Ah_g,
    const h16* __restrict__ Wh_g, const h16* __restrict__ Wl_g,
    float* __restrict__ Cf, h16* __restrict__ Ch, h16* __restrict__ Cl,
    int mode, int comp)
{
    extern __shared__ __align__(16) unsigned char dynsm[];
    h16* sA = (h16*)dynsm;                    // [3][128][40]
    h16* sW = sA + 3*128*40;                  // [2][3][64][40]

    const int tid = threadIdx.x, lane = tid & 31, wid = tid >> 5;
    const int wm = wid >> 1, wn = wid & 1;
    const int g = lane >> 2, t = lane & 3;
    const int m0 = blockIdx.y * 128, n0 = blockIdx.x * 64;

    const uns as_a = smem_u32(sA);
    const uns ws_a = smem_u32(sW);
    const int arow = AROW(lane), acol = ACOL(lane);
    const int brow = BROW(lane), bcol = BCOL(lane);

    float acc[2][4][4];
    #pragma unroll
    for (int i=0;i<2;i++)
        #pragma unroll
        for (int j=0;j<4;j++)
            #pragma unroll
            for (int e=0;e<4;e++) acc[i][j][e]=0.f;

    auto pre = [&](int kt, int st){
        const int k0 = kt * 32;
        #pragma unroll
        for (int i = 0; i < 2; i++){
            int idx = tid + i*256;
            int r = idx >> 2, c = idx & 3;
            CP16(smem_u32(sA + st*5120 + r*40 + c*8),
                 Ah_g + (size_t)(m0+r)*DD + k0 + c*8);
        }
        if (comp){
            #pragma unroll
            for (int i = 0; i < 2; i++){
                int idx = tid + i*256;
                int pl = idx >> 8, rem = idx & 255;
                int r = rem >> 2, c = rem & 3;
                CP16(smem_u32(sW + (pl*3+st)*2560 + r*40 + c*8),
                     (pl ? Wl_g : Wh_g) + (size_t)(n0+r)*DD + k0 + c*8);
            }
        } else {
            int r = tid >> 2, c = tid & 3;
            CP16(smem_u32(sW + st*2560 + r*40 + c*8),
                 Wh_g + (size_t)(n0+r)*DD + k0 + c*8);
        }
        CPCOMMIT();
    };

    pre(0, 0);
    pre(1, 1);
    const int NT = DD / 32;   // 32
    for (int kt = 0; kt < NT; kt++){
        const int st = kt % 3;
        if (kt + 1 < NT){ CPWAIT(1); } else { CPWAIT(0); }
        __syncthreads();

        #pragma unroll
        for (int ks = 0; ks < 2; ks++){
            const int k0 = ks*16;
            uns ah[2][4];
            #pragma unroll
            for (int mt = 0; mt < 2; mt++)
                ldm4(ah[mt], as_a + ((st*128 + wm*32 + mt*16 + arow)*40
                                     + k0 + acol)*2);
            uns bhq[2][4], blq[2][4];
            #pragma unroll
            for (int hq = 0; hq < 2; hq++){
                ldm4(bhq[hq], ws_a + (((0*3+st)*64 + wn*32 + hq*16 + brow)*40
                                      + k0 + bcol)*2);
                if (comp)
                    ldm4(blq[hq], ws_a + (((1*3+st)*64 + wn*32 + hq*16 + brow)*40
                                          + k0 + bcol)*2);
            }
            #pragma unroll
            for (int mt = 0; mt < 2; mt++)
                #pragma unroll
                for (int nt = 0; nt < 4; nt++){
                    const int hq = nt >> 1, p = (nt & 1) * 2;
                    mma_f16(acc[mt][nt], ah[mt], bhq[hq][p], bhq[hq][p+1]);
                    if (comp)
                        mma_f16(acc[mt][nt], ah[mt], blq[hq][p], blq[hq][p+1]);
                }
        }
        if (kt + 2 < NT) pre(kt + 2, (kt + 2) % 3);
    }

    if (mode == 0){
        #pragma unroll
        for (int mt = 0; mt < 2; mt++)
            #pragma unroll
            for (int nt = 0; nt < 4; nt++){
                const int r0 = m0 + wm*32 + mt*16 + g;
                const int r1 = r0 + 8;
                const int cb = n0 + wn*32 + nt*8 + 2*t;
                float* a = acc[mt][nt];
                *(float2*)&Cf[(size_t)r0*DD + cb] = make_float2(a[0], a[1]);
                *(float2*)&Cf[(size_t)r1*DD + cb] = make_float2(a[2], a[3]);
            }
        return;
    }

    if (mode == 1 || mode == 2){
        #pragma unroll
        for (int mt = 0; mt < 2; mt++)
            #pragma unroll
            for (int nt = 0; nt < 4; nt++){
                const int r0 = m0 + wm*32 + mt*16 + g;
                const int r1 = r0 + 8;
                const int cb = n0 + wn*32 + nt*8 + 2*t;
                const int h = cb >> 6, dh = cb & 63;
                float* a = acc[mt][nt];
                #pragma unroll
                for (int p = 0; p < 2; p++){
                    int m = p ? r1 : r0;
                    int b = m >> 11, sq = m & (SS - 1);
                    size_t base = (((size_t)(b*HH + h))*SS + sq)*DH + dh;
                    float x0 = a[p*2], x1 = a[p*2+1];
                    if (mode == 1){
                        *(uns*)&Ch[base] = pkf(x0, x1);
                    } else {
                        h16 h0,l0,h1,l1;
                        hsplit(x0,h0,l0); hsplit(x1,h1,l1);
                        *(uns*)&Ch[base] = pkh(h0,h1);
                        *(uns*)&Cl[base] = pkh(l0,l1);
                    }
                }
            }
    } else {  // mode 3: transposed hi-only [BH,DH,S], staged coalesced
        const int b = m0 >> 11, sq0 = m0 & (SS-1), h = n0 >> 6;
        h16* stg = sA;   // [64][136]
        __syncthreads();           // all warps done reading operand smem
        #pragma unroll
        for (int mt = 0; mt < 2; mt++)
            #pragma unroll
            for (int nt = 0; nt < 4; nt++){
                float* a = acc[mt][nt];
                #pragma unroll
                for (int e = 0; e < 4; e++){
                    int dh = wn*32 + nt*8 + 2*t + (e & 1);
                    int ml = wm*32 + mt*16 + g + ((e < 2) ? 0 : 8);
                    stg[dh*136 + ml] = __float2half_rn(a[e]);
                }
            }
        __syncthreads();
        #pragma unroll
        for (int i = 0; i < 4; i++){          // 1024 uint4
            int idx = tid + i*256;
            int r = idx >> 4, c = idx & 15;
            *(uint4*)&Ch[((size_t)(b*HH + h)*DH + r)*SS + sq0 + c*8]
                = *(uint4*)&stg[r*136 + c*8];
        }
    }
}

// ---------------------------------------------------------------------------
// Fused scores + mask + softmax. Q hi, K hi (plain fp16 QK^T).
// 3-stage K pipeline, ONE barrier per K-block. Sum pass without writeback;
// exp recomputed fused with the final write (bit-identical).
// dyn smem: ps[16][2052]f32 + q[16][72]h + k[3][128][72]h
//           + invs[16] + mxs[16] + wmax[16][8] = 189568 B
// ---------------------------------------------------------------------------
#define SC_SMEM (16*2052*4 + 16*72*2 + 3*128*72*2 + 64 + 64 + 512)

__global__ __launch_bounds__(256) void scores_softmax(
    const h16* __restrict__ Qh_g,
    const h16* __restrict__ Kh_g,
    float* __restrict__ attn, h16* __restrict__ p16)
{
    extern __shared__ __align__(16) unsigned char dynsm[];
    float* ps  = (float*)dynsm;
    h16* qsm   = (h16*)(dynsm + 16*2052*4);
    h16* ksm   = (h16*)(dynsm + 16*2052*4 + 16*72*2);
    float* invs= (float*)(dynsm + 16*2052*4 + 16*72*2 + 3*128*72*2);
    float* mxs = invs + 16;
    float* wmax= mxs + 16;                        // [16][8]

    const int tid = threadIdx.x, lane = tid & 31, wid = tid >> 5;
    const int g = lane >> 2, t = lane & 3;
    const int bh = blockIdx.y, q0 = blockIdx.x * 16;

    const uns q_a = smem_u32(qsm);
    const uns k_a = smem_u32(ksm);
    const int arow = AROW(lane), acol = ACOL(lane);
    const int brow = BROW(lane), bcol = BCOL(lane);

    // stage Q tile hi plane (16x64): 128 chunks (own commit group 0... merged
    // with first preK group is fine: both needed before first compute)
    if (tid < 128){
        int r = tid >> 3, c = tid & 7;
        CP16(smem_u32(qsm + r*72 + c*8),
             Qh_g + ((size_t)bh*SS + q0 + r)*DH + c*8);
    }

    auto preK = [&](int kb, int st){
        #pragma unroll
        for (int i = 0; i < 4; i++){      // 1024 chunks (128r x 8c)
            int idx = tid + i*256;
            int r = idx >> 3, c = idx & 7;
            CP16(smem_u32(ksm + (st*128 + r)*72 + c*8),
                 Kh_g + ((size_t)bh*SS + kb*128 + r)*DH + c*8);
        }
        CPCOMMIT();
    };

    preK(0, 0);          // group 0 (includes Q staging)
    preK(1, 1);          // group 1

    uns qa[4][4];
    const int nbase = wid * 16;
    float mr0 = -3.0e38f, mr8 = -3.0e38f;

    for (int kb = 0; kb < 16; kb++){
        const int st = kb % 3;
        if (kb + 1 < 16){ CPWAIT(1); } else { CPWAIT(0); }
        __syncthreads();

        if (kb == 0){
            #pragma unroll
            for (int ck = 0; ck < 4; ck++)
                ldm4(qa[ck], q_a + (arow*72 + ck*16 + acol)*2);
        }

        float acc[2][4] = {{0.f,0.f,0.f,0.f},{0.f,0.f,0.f,0.f}};
        #pragma unroll
        for (int ck = 0; ck < 4; ck++){
            uns bh2[4];
            ldm4(bh2, k_a + ((st*128 + nbase + brow)*72 + ck*16 + bcol)*2);
            mma_f16(acc[0], qa[ck], bh2[0], bh2[1]);
            mma_f16(acc[1], qa[ck], bh2[2], bh2[3]);
        }

        // scale + mask + ps write + running max
        #pragma unroll
        for (int nt = 0; nt < 2; nt++){
            const int col = kb*128 + nbase + nt*8 + 2*t;
            const unsigned w0 = g_mbits[((size_t)(q0 + g    )*SS + col) >> 5];
            const unsigned w8 = g_mbits[((size_t)(q0 + g + 8)*SS + col) >> 5];
            const int sh = col & 31;
            float s0 = ((w0 >> sh)     & 1) ? acc[nt][0]*0.125f : -1e34f;
            float s1 = ((w0 >> (sh+1)) & 1) ? acc[nt][1]*0.125f : -1e34f;
            float s2 = ((w8 >> sh)     & 1) ? acc[nt][2]*0.125f : -1e34f;
            float s3 = ((w8 >> (sh+1)) & 1) ? acc[nt][3]*0.125f : -1e34f;
            ps[(g    )*2052 + col    ] = s0;
            ps[(g    )*2052 + col + 1] = s1;
            ps[(g + 8)*2052 + col    ] = s2;
            ps[(g + 8)*2052 + col + 1] = s3;
            mr0 = fmaxf(mr0, fmaxf(s0, s1));
            mr8 = fmaxf(mr8, fmaxf(s2, s3));
        }
        if (kb + 2 < 16) preK(kb + 2, (kb + 2) % 3);
    }

    #pragma unroll
    for (int off = 1; off < 4; off <<= 1){
        mr0 = fmaxf(mr0, __shfl_xor_sync(0xffffffffu, mr0, off));
        mr8 = fmaxf(mr8, __shfl_xor_sync(0xffffffffu, mr8, off));
    }
    if (t == 0){
        wmax[(g    )*8 + wid] = mr0;
        wmax[(g + 8)*8 + wid] = mr8;
    }
    __syncthreads();

    // sum pass: 16 threads per row, NO writeback
    {
        const int row = tid >> 4, sub = tid & 15;
        const float* pr = ps + row * 2052;
        float mx = -3.0e38f;
        #pragma unroll
        for (int j = 0; j < 8; j++) mx = fmaxf(mx, wmax[row*8 + j]);
        float sum = 0.f;
        for (int k2 = sub; k2 < SS; k2 += 16)
            sum += __expf(pr[k2] - mx);
        #pragma unroll
        for (int off = 1; off < 16; off <<= 1)
            sum += __shfl_xor_sync(0xffffffffu, sum, off);
        if (sub == 0){ invs[row] = 1.f / sum; mxs[row] = mx; }
    }
    __syncthreads();

    // fused exp + write (attn f32 + p16)
    float* Ar = attn + ((size_t)bh * SS + q0) * SS;
    h16*   Pr = p16  + ((size_t)bh * SS + q0) * SS;
    #pragma unroll
    for (int i = 0; i < 32; i++){
        int idx = tid + i * 256;
        int r = idx >> 9, c4 = idx & 511;
        float inv = invs[r], mx = mxs[r];
        float4 v = *(float4*)&ps[r * 2052 + c4 * 4];
        v.x = __expf(v.x - mx) * inv;
        v.y = __expf(v.y - mx) * inv;
        v.z = __expf(v.z - mx) * inv;
        v.w = __expf(v.w - mx) * inv;
        *(float4*)&Ar[(size_t)r * SS + c4 * 4] = v;
        *(uint2*)&Pr[(size_t)r * SS + c4 * 4] = make_uint2(pkf(v.x, v.y),
                                                           pkf(v.z, v.w));
    }
}

// ---------------------------------------------------------------------------
// ctx = P16 @ V (plain fp16: V hi only). 3-stage pipeline, ONE barrier/iter.
// dyn smem: Ps[3][128][72]h + Vs[3][64][72]h = 82944 B
// ---------------------------------------------------------------------------
#define CTX_SMEM (3*128*72*2 + 3*64*72*2)

__global__ __launch_bounds__(256) void ctx_mma(
    const h16* __restrict__ P16,
    const h16* __restrict__ Vh_g,
    h16* __restrict__ Ch)
{
    extern __shared__ __align__(16) unsigned char dynsm[];
    h16* Psm = (h16*)dynsm;                    // [3][128][72]
    h16* Vsm = (h16*)(dynsm + 3*128*72*2);     // [3][64][72]

    const int tid = threadIdx.x, lane = tid & 31, wid = tid >> 5;
    const int wm = wid >> 1, wn = wid & 1;
    const int g = lane >> 2, t = lane & 3;
    const int bh = blockIdx.y, q0 = blockIdx.x * 128;

    const uns p_a = smem_u32(Psm);
    const uns v_a = smem_u32(Vsm);
    const int arow = AROW(lane), acol = ACOL(lane);
    const int brow = BROW(lane), bcol = BCOL(lane);

    const h16* Pb  = P16  + (size_t)bh * SS * SS;
    const h16* Vhb = Vh_g + (size_t)bh * DH * SS;

    float acc[2][4][4];
    #pragma unroll
    for (int i=0;i<2;i++)
        #pragma unroll
        for (int j=0;j<4;j++)
            #pragma unroll
            for (int e=0;e<4;e++) acc[i][j][e]=0.f;

    auto pre = [&](int kt, int st){
        const int k0 = kt * 64;
        #pragma unroll
        for (int i = 0; i < 4; i++){           // P: 1024 chunks (128r x 8c)
            int idx = tid + i*256;
            int r = idx >> 3, c = idx & 7;
            CP16(smem_u32(Psm + (st*128 + r)*72 + c*8),
                 Pb + (size_t)(q0 + r)*SS + k0 + c*8);
        }
        #pragma unroll
        for (int i = 0; i < 2; i++){           // V: 512 chunks (64r x 8c)
            int idx = tid + i*256;
            int r = idx >> 3, c = idx & 7;
            CP16(smem_u32(Vsm + (st*64 + r)*72 + c*8),
                 Vhb + (size_t)r*SS + k0 + c*8);
        }
        CPCOMMIT();
    };

    pre(0, 0);
    pre(1, 1);
    const int NT = SS / 64;   // 32
    for (int kt = 0; kt < NT; kt++){
        const int st = kt % 3;
        if (kt + 1 < NT){ CPWAIT(1); } else { CPWAIT(0); }
        __syncthreads();

        #pragma unroll
        for (int ks = 0; ks < 4; ks++){
            const int k0 = ks*16;
            uns ah[2][4];
            #pragma unroll
            for (int mt = 0; mt < 2; mt++)
                ldm4(ah[mt], p_a + ((st*128 + wm*32 + mt*16 + arow)*72
                                    + k0 + acol)*2);
            uns bhq[2][4];
            #pragma unroll
            for (int hq = 0; hq < 2; hq++)
                ldm4(bhq[hq], v_a + ((st*64 + wn*32 + hq*16 + brow)*72
                                     + k0 + bcol)*2);
            #pragma unroll
            for (int mt = 0; mt < 2; mt++)
                #pragma unroll
                for (int nt = 0; nt < 4; nt++){
                    const int hq = nt >> 1, p = (nt & 1) * 2;
                    mma_f16(acc[mt][nt], ah[mt], bhq[hq][p], bhq[hq][p+1]);
                }
        }
        if (kt + 2 < NT) pre(kt + 2, (kt + 2) % 3);
    }

    const int b = bh >> 4, h = bh & 15;
    #pragma unroll
    for (int mt = 0; mt < 2; mt++){
        #pragma unroll
        for (int nt = 0; nt < 4; nt++){
            const int r0 = q0 + wm*32 + mt*16 + g;
            const int r1 = r0 + 8;
            const int cb = h*64 + wn*32 + nt*8 + 2*t;
            float* a = acc[mt][nt];
            *(uns*)&Ch[(size_t)(b*SS + r0)*DD + cb] = pkf(a[0], a[1]);
            *(uns*)&Ch[(size_t)(b*SS + r1)*DD + cb] = pkf(a[2], a[3]);
        }
    }
}

// ---------------------------------------------------------------------------
extern "C" void kernel_launch(void* const* d_in, const int* in_sizes, int n_in,
                              void* d_out, int out_size)
{
    const float* q    = (const float*)d_in[0];
    const float* k    = (const float*)d_in[1];
    const float* v    = (const float*)d_in[2];
    const int*   mask = (const int*)  d_in[3];
    const float* Wq   = (const float*)d_in[4];
    const float* Wk   = (const float*)d_in[5];
    const float* Wv   = (const float*)d_in[6];
    const float* Wo   = (const float*)d_in[7];

    float* out  = (float*)d_out;               // [B,S,D]
    float* attn = out + (size_t)MM * DD;       // [B,H,S,S]

    h16* P; cudaGetSymbolAddress((void**)&P, g_hf);
    h16* p16; cudaGetSymbolAddress((void**)&p16, g_p16);
    h16 *xa_h = P + (size_t)0*CHK;
    h16 *xb_h = P + (size_t)1*CHK;
    h16 *xc_h = P + (size_t)2*CHK;
    h16 *qh_h = P + (size_t)3*CHK;
    h16 *kh_h = P + (size_t)4*CHK;
    h16 *vt_h = P + (size_t)6*CHK;
    h16 *cx_h = P + (size_t)8*CHK;
    h16 *wb   = P + (size_t)9*CHK;
    h16 *wq_h = wb + (size_t)0*WCH, *wq_l = wb + (size_t)1*WCH;
    h16 *wk_h = wb + (size_t)2*WCH, *wk_l = wb + (size_t)3*WCH;
    h16 *wv_h = wb + (size_t)4*WCH;
    h16 *wo_h = wb + (size_t)6*WCH, *wo_l = wb + (size_t)7*WCH;

    cudaFuncSetAttribute(proj_mma,
        cudaFuncAttributeMaxDynamicSharedMemorySize, PROJ_SMEM);
    cudaFuncSetAttribute(scores_softmax,
        cudaFuncAttributeMaxDynamicSharedMemorySize, SC_SMEM);
    cudaFuncSetAttribute(ctx_mma,
        cudaFuncAttributeMaxDynamicSharedMemorySize, CTX_SMEM);

    split_act<<<dim3(MM*DD/1024, 3), 256>>>(q, k, v, P);
    split_w  <<<dim3(DD*DD/1024, 4), 256>>>(Wq, Wk, Wv, Wo, wb);
    maskpack_kernel<<<SS*SS/256, 256>>>(mask);

    dim3 gproj(DD / 64, MM / 128);   // (16, 32)

    proj_mma<<<gproj, 256, PROJ_SMEM>>>(xa_h, wq_h, wq_l, nullptr, qh_h, nullptr, 1, 1);
    proj_mma<<<gproj, 256, PROJ_SMEM>>>(xb_h, wk_h, wk_l, nullptr, kh_h, nullptr, 1, 1);

    scores_softmax<<<dim3(SS/16, BH), 256, SC_SMEM>>>(qh_h, kh_h, attn, p16);

    proj_mma<<<gproj, 256, PROJ_SMEM>>>(xc_h, wv_h, nullptr, nullptr, vt_h, nullptr, 3, 0);

    ctx_mma<<<dim3(SS/128, BH), 256, CTX_SMEM>>>(p16, vt_h, cx_h);

    proj_mma<<<gproj, 256, PROJ_SMEM>>>(cx_h, wo_h, wo_l, out, nullptr, nullptr, 0, 1);
}